// round 15
// baseline (speedup 1.0000x reference)
#include <cuda_runtime.h>
#include <cuda_bf16.h>
#include <cstdint>
#include <math.h>

// Problem shape (fixed by setup_inputs)
#define Bn 2048
#define Kn 256
#define Dn 512
#define NCTA 128        // persistent grid; co-resident (<= #SMs, 96KB smem)

// bf16 staging buffers (__device__ globals: allocation-free)
__device__ __nv_bfloat16 g_abig[Bn * 1024];  // [b][ x^2(512) | x(512) ]
__device__ __nv_bfloat16 g_bmat[Kn * 1024];  // [k][ bw(512) | -2bw*c(512) ]
__device__ __nv_bfloat16 g_rbf [Bn * Kn];    // rbf, K-major
__device__ __nv_bfloat16 g_wt  [Dn * Kn];    // softplus(W)^T: [d][k]
__device__ float         g_ck  [Kn];         // sum_d bw*c^2
__device__ unsigned g_count, g_done, g_anynz; // barrier + sparsity flag

// ---------------------------------------------------------------------------
// Helpers (arch-generic: ldmatrix / mma.sync / cp.async — NO tcgen05)
// ---------------------------------------------------------------------------
__device__ __forceinline__ uint32_t s2u(const void* p) {
    uint32_t a;
    asm("{ .reg .u64 t; cvta.to.shared.u64 t, %1; cvt.u32.u64 %0, t; }"
        : "=r"(a) : "l"(p));
    return a;
}
#define SW128(o) ((o) ^ (((o) >> 3) & 0x70))

__device__ __forceinline__ void cp16(uint32_t s, const void* g) {
    asm volatile("cp.async.cg.shared.global [%0], [%1], 16;" :: "r"(s), "l"(g));
}

__device__ __forceinline__ void ldsm4(uint32_t* r, uint32_t addr) {
    asm volatile("ldmatrix.sync.aligned.m8n8.x4.shared.b16 {%0,%1,%2,%3}, [%4];"
                 : "=r"(r[0]), "=r"(r[1]), "=r"(r[2]), "=r"(r[3]) : "r"(addr));
}

__device__ __forceinline__ void mma16816(float* c, const uint32_t* a, const uint32_t* b) {
    asm volatile(
        "mma.sync.aligned.m16n8k16.row.col.f32.bf16.bf16.f32 "
        "{%0,%1,%2,%3}, {%4,%5,%6,%7}, {%8,%9}, {%0,%1,%2,%3};"
        : "+f"(c[0]), "+f"(c[1]), "+f"(c[2]), "+f"(c[3])
        : "r"(a[0]), "r"(a[1]), "r"(a[2]), "r"(a[3]), "r"(b[0]), "r"(b[1]));
}

__device__ __forceinline__ uint32_t bits2(__nv_bfloat162 v) {
    return *(uint32_t*)&v;
}

__device__ __forceinline__ void gridbar(unsigned target) {
    __threadfence();
    __syncthreads();
    if (threadIdx.x == 0) {
        atomicAdd(&g_count, 1u);
        while (atomicAdd(&g_count, 0u) < target) { }
    }
    __syncthreads();
    __threadfence();
}

// ---------------------------------------------------------------------------
// GEMM tile body (R11/R14 known-good: split-K 2 warp-groups, register-
// pipelined fragments). G1 epilogue raises g_anynz if any rbf value != 0.
// ---------------------------------------------------------------------------
#define STAGE_BYTES 16384
#define NSTAGE 6
#define SMEMSZ (NSTAGE * STAGE_BYTES)   // 98304 (G2 path uses first 4 stages)

template<bool ISG2>
__device__ __forceinline__ void gemm_tile(char* sm, int m0, int n0,
                                          float* __restrict__ out) {
    constexpr int LD     = ISG2 ? 256 : 1024;
    constexpr int NCHUNK = ISG2 ? 4   : 16;
    constexpr int NSTEP  = NCHUNK / 2;
    constexpr int NST    = ISG2 ? 4 : 6;
    const __nv_bfloat16* __restrict__ A  = ISG2 ? g_rbf : g_abig;
    const __nv_bfloat16* __restrict__ Bm = ISG2 ? g_wt  : g_bmat;

    const uint32_t T0 = s2u(sm);
    const int tid = threadIdx.x, wid = tid >> 5, l = tid & 31;
    const int grp = wid >> 2, wg = wid & 3;
    const int wm = wg & 1, wn = wg >> 1;

    const int lr = l & 7, sel = l >> 3;
    const int a_row = wm * 32 + (sel & 1) * 8 + lr;
    const uint32_t a_kb = (uint32_t)((sel >> 1) * 16);
    const int b_row = wn * 32 + (sel >> 1) * 8 + lr;
    const uint32_t b_kb = (uint32_t)((sel & 1) * 16);

    __syncthreads();   // protect smem from previous phase/tile

    #define LOAD_CHUNK(ch) do {                                              \
        uint32_t _sa = T0 + ((ch) % NST) * STAGE_BYTES;                      \
        const __nv_bfloat16* _ga = A  + (size_t)m0 * LD + (ch) * 64;         \
        const __nv_bfloat16* _gb = Bm + (size_t)n0 * LD + (ch) * 64;         \
        _Pragma("unroll")                                                    \
        for (int q = 0; q < 2; q++) {                                        \
            int r = (tid + q * 256) >> 3, cc = (tid + q * 256) & 7;          \
            uint32_t off = SW128((uint32_t)(r * 128 + cc * 16));             \
            cp16(_sa        + off, _ga + (size_t)r * LD + cc * 8);           \
            cp16(_sa + 8192 + off, _gb + (size_t)r * LD + cc * 8);           \
        }                                                                    \
    } while (0)

    #define LOAD_PAIR(p) do {                                                \
        LOAD_CHUNK(2 * (p));  LOAD_CHUNK(2 * (p) + 1);                       \
        asm volatile("cp.async.commit_group;");                              \
    } while (0)

    #define LDFRAG(sa, sbb, ks, buf) do {                                    \
        _Pragma("unroll")                                                    \
        for (int mi = 0; mi < 2; mi++)                                       \
            ldsm4(af[buf][mi], (sa) + SW128((uint32_t)((a_row + mi * 16) * 128) \
                                            + (uint32_t)((ks) * 32) + a_kb)); \
        _Pragma("unroll")                                                    \
        for (int bi = 0; bi < 2; bi++)                                       \
            ldsm4(bf[buf][bi], (sbb) + SW128((uint32_t)((b_row + bi * 16) * 128) \
                                             + (uint32_t)((ks) * 32) + b_kb)); \
    } while (0)

    float acc[2][4][4];
    #pragma unroll
    for (int mi = 0; mi < 2; mi++)
        #pragma unroll
        for (int nj = 0; nj < 4; nj++)
            #pragma unroll
            for (int e = 0; e < 4; e++) acc[mi][nj][e] = 0.0f;

    LOAD_PAIR(0);
    if (NSTEP > 1) LOAD_PAIR(1);

    uint32_t af[2][2][4], bf[2][2][4];

    for (int t = 0; t < NSTEP; t++) {
        if (t < NSTEP - 1) asm volatile("cp.async.wait_group 1;");
        else               asm volatile("cp.async.wait_group 0;");
        __syncthreads();
        if (t + 2 < NSTEP) LOAD_PAIR(t + 2);

        const int ch = 2 * t + grp;
        const uint32_t sa  = T0 + (ch % NST) * STAGE_BYTES;
        const uint32_t sbb = sa + 8192;

        LDFRAG(sa, sbb, 0, 0);
        #pragma unroll
        for (int ks = 0; ks < 4; ks++) {
            const int cur = ks & 1;
            if (ks < 3) LDFRAG(sa, sbb, ks + 1, cur ^ 1);
            #pragma unroll
            for (int mi = 0; mi < 2; mi++)
                #pragma unroll
                for (int nj = 0; nj < 4; nj++)
                    mma16816(acc[mi][nj], af[cur][mi], &bf[cur][nj >> 1][(nj & 1) * 2]);
        }
    }
    #undef LDFRAG
    #undef LOAD_PAIR
    #undef LOAD_CHUNK

    // ---- cross-group reduce through smem (pitch 72 floats) ---------------
    float* Rb = (float*)sm;
    const int rrow = wm * 32 + (l >> 2);
    const int rcol = wn * 32 + 2 * (l & 3);
    __syncthreads();
    if (grp == 1) {
        #pragma unroll
        for (int mi = 0; mi < 2; mi++)
            #pragma unroll
            for (int nj = 0; nj < 4; nj++) {
                const int r = rrow + mi * 16, c = rcol + nj * 8;
                *(float2*)&Rb[r * 72 + c]       = make_float2(acc[mi][nj][0], acc[mi][nj][1]);
                *(float2*)&Rb[(r + 8) * 72 + c] = make_float2(acc[mi][nj][2], acc[mi][nj][3]);
            }
    }
    __syncthreads();

    int nzpred = 0;
    if (grp == 0) {
        #pragma unroll
        for (int mi = 0; mi < 2; mi++)
            #pragma unroll
            for (int nj = 0; nj < 4; nj++) {
                const int r = rrow + mi * 16, c = rcol + nj * 8;
                float2 p0 = *(const float2*)&Rb[r * 72 + c];
                float2 p1 = *(const float2*)&Rb[(r + 8) * 72 + c];
                acc[mi][nj][0] += p0.x;  acc[mi][nj][1] += p0.y;
                acc[mi][nj][2] += p1.x;  acc[mi][nj][3] += p1.y;
            }

        const int erow = m0 + rrow;
        if (!ISG2) {
            #pragma unroll
            for (int mi = 0; mi < 2; mi++) {
                #pragma unroll
                for (int nj = 0; nj < 4; nj++) {
                    const int col = rcol + nj * 8;
                    const float ck0 = g_ck[n0 + col];
                    const float ck1 = g_ck[n0 + col + 1];
                    const int r = erow + mi * 16;
                    float v0 = __expf(-0.5f * (acc[mi][nj][0] + ck0));
                    float v1 = __expf(-0.5f * (acc[mi][nj][1] + ck1));
                    float v2 = __expf(-0.5f * (acc[mi][nj][2] + ck0));
                    float v3 = __expf(-0.5f * (acc[mi][nj][3] + ck1));
                    nzpred |= (v0 != 0.0f) | (v1 != 0.0f) | (v2 != 0.0f) | (v3 != 0.0f);
                    __nv_bfloat162 p0 = __floats2bfloat162_rn(v0, v1);
                    __nv_bfloat162 p1 = __floats2bfloat162_rn(v2, v3);
                    *(__nv_bfloat162*)&g_rbf[(size_t)r * Kn + n0 + col]       = p0;
                    *(__nv_bfloat162*)&g_rbf[(size_t)(r + 8) * Kn + n0 + col] = p1;
                }
            }
        } else {
            const float eps = 1e-3f;
            #pragma unroll
            for (int mi = 0; mi < 2; mi++) {
                #pragma unroll
                for (int nj = 0; nj < 4; nj++) {
                    const int col = n0 + rcol + nj * 8;
                    const int r = erow + mi * 16;
                    float2 o0, o1;
                    o0.x = __fdividef(1.0f, acc[mi][nj][0] + eps);
                    o0.y = __fdividef(1.0f, acc[mi][nj][1] + eps);
                    o1.x = __fdividef(1.0f, acc[mi][nj][2] + eps);
                    o1.y = __fdividef(1.0f, acc[mi][nj][3] + eps);
                    *(float2*)(out + (size_t)r * Dn + col)       = o0;
                    *(float2*)(out + (size_t)(r + 8) * Dn + col) = o1;
                }
            }
        }
    }

    if (!ISG2) {
        int any = __syncthreads_or(nzpred);
        if (any && tid == 0) atomicOr(&g_anynz, 1u);
    }
    __syncthreads();
}

// ---------------------------------------------------------------------------
// ONE persistent kernel: phase0 prep (global staging, R10-style) -> gridbar
// -> G1 (+nz detect) -> gridbar -> G2 (zero fast-path / full fallback).
// 128 CTAs x 256 threads, 96KB dynamic smem.
// ---------------------------------------------------------------------------
__global__ void __launch_bounds__(256, 1)
mega_kern(const float* __restrict__ x, const float* __restrict__ centers,
          const float* __restrict__ bandwidths, const float* __restrict__ raw,
          float* __restrict__ out) {
    extern __shared__ char sm[];
    const int c = blockIdx.x, tid = threadIdx.x;

    // ================= Phase 0: prep =================
    // prepA: 512 units of (256 thr x 16 elems); CTA c does units 2c, 2c+1
    #pragma unroll
    for (int uu = 0; uu < 2; uu++) {
        const int e = ((c * 2 + uu) * 256 + tid) * 16;
        const int row = e >> 9;
        const int d = e & 511;
        const float4* src = (const float4*)(x + e);
        float4 v0 = src[0], v1 = src[1], v2 = src[2], v3 = src[3];
        uint4 sq0, sq1, xx0, xx1;
        sq0.x = bits2(__floats2bfloat162_rn(v0.x * v0.x, v0.y * v0.y));
        sq0.y = bits2(__floats2bfloat162_rn(v0.z * v0.z, v0.w * v0.w));
        sq0.z = bits2(__floats2bfloat162_rn(v1.x * v1.x, v1.y * v1.y));
        sq0.w = bits2(__floats2bfloat162_rn(v1.z * v1.z, v1.w * v1.w));
        sq1.x = bits2(__floats2bfloat162_rn(v2.x * v2.x, v2.y * v2.y));
        sq1.y = bits2(__floats2bfloat162_rn(v2.z * v2.z, v2.w * v2.w));
        sq1.z = bits2(__floats2bfloat162_rn(v3.x * v3.x, v3.y * v3.y));
        sq1.w = bits2(__floats2bfloat162_rn(v3.z * v3.z, v3.w * v3.w));
        xx0.x = bits2(__floats2bfloat162_rn(v0.x, v0.y));
        xx0.y = bits2(__floats2bfloat162_rn(v0.z, v0.w));
        xx0.z = bits2(__floats2bfloat162_rn(v1.x, v1.y));
        xx0.w = bits2(__floats2bfloat162_rn(v1.z, v1.w));
        xx1.x = bits2(__floats2bfloat162_rn(v2.x, v2.y));
        xx1.y = bits2(__floats2bfloat162_rn(v2.z, v2.w));
        xx1.z = bits2(__floats2bfloat162_rn(v3.x, v3.y));
        xx1.w = bits2(__floats2bfloat162_rn(v3.z, v3.w));
        uint4* dsq = (uint4*)&g_abig[row * 1024 + d];
        uint4* dxx = (uint4*)&g_abig[row * 1024 + 512 + d];
        dsq[0] = sq0;  dsq[1] = sq1;
        dxx[0] = xx0;  dxx[1] = xx1;
    }

    // prepB + ck: 32 units; CTAs 0..31 (one warp per k-row)
    if (c < 32) {
        const int e = (c * 256 + tid) * 16;
        const int k = e >> 9;
        const int d = e & 511;
        const float4* sb = (const float4*)(bandwidths + e);
        const float4* sc = (const float4*)(centers + e);
        float4 b0 = sb[0], b1 = sb[1], b2 = sb[2], b3 = sb[3];
        float4 c0 = sc[0], c1 = sc[1], c2 = sc[2], c3 = sc[3];
        uint4 wb0, wb1, wc0, wc1;
        wb0.x = bits2(__floats2bfloat162_rn(b0.x, b0.y));
        wb0.y = bits2(__floats2bfloat162_rn(b0.z, b0.w));
        wb0.z = bits2(__floats2bfloat162_rn(b1.x, b1.y));
        wb0.w = bits2(__floats2bfloat162_rn(b1.z, b1.w));
        wb1.x = bits2(__floats2bfloat162_rn(b2.x, b2.y));
        wb1.y = bits2(__floats2bfloat162_rn(b2.z, b2.w));
        wb1.z = bits2(__floats2bfloat162_rn(b3.x, b3.y));
        wb1.w = bits2(__floats2bfloat162_rn(b3.z, b3.w));
        wc0.x = bits2(__floats2bfloat162_rn(-2.0f * b0.x * c0.x, -2.0f * b0.y * c0.y));
        wc0.y = bits2(__floats2bfloat162_rn(-2.0f * b0.z * c0.z, -2.0f * b0.w * c0.w));
        wc0.z = bits2(__floats2bfloat162_rn(-2.0f * b1.x * c1.x, -2.0f * b1.y * c1.y));
        wc0.w = bits2(__floats2bfloat162_rn(-2.0f * b1.z * c1.z, -2.0f * b1.w * c1.w));
        wc1.x = bits2(__floats2bfloat162_rn(-2.0f * b2.x * c2.x, -2.0f * b2.y * c2.y));
        wc1.y = bits2(__floats2bfloat162_rn(-2.0f * b2.z * c2.z, -2.0f * b2.w * c2.w));
        wc1.z = bits2(__floats2bfloat162_rn(-2.0f * b3.x * c3.x, -2.0f * b3.y * c3.y));
        wc1.w = bits2(__floats2bfloat162_rn(-2.0f * b3.z * c3.z, -2.0f * b3.w * c3.w));
        uint4* db = (uint4*)&g_bmat[k * 1024 + d];
        uint4* dc = (uint4*)&g_bmat[k * 1024 + 512 + d];
        db[0] = wb0;  db[1] = wb1;
        dc[0] = wc0;  dc[1] = wc1;
        float s = b0.x * c0.x * c0.x + b0.y * c0.y * c0.y
                + b0.z * c0.z * c0.z + b0.w * c0.w * c0.w
                + b1.x * c1.x * c1.x + b1.y * c1.y * c1.y
                + b1.z * c1.z * c1.z + b1.w * c1.w * c1.w
                + b2.x * c2.x * c2.x + b2.y * c2.y * c2.y
                + b2.z * c2.z * c2.z + b2.w * c2.w * c2.w
                + b3.x * c3.x * c3.x + b3.y * c3.y * c3.y
                + b3.z * c3.z * c3.z + b3.w * c3.w * c3.w;
        #pragma unroll
        for (int o = 16; o > 0; o >>= 1)
            s += __shfl_down_sync(0xffffffffu, s, o);
        if ((tid & 31) == 0) g_ck[k] = s;
    }

    // prepW: 128 tiles; CTA c does tile c (static smem scratch)
    {
        const int d0 = (c & 15) * 32, k0 = (c >> 4) * 32;
        const int tx = tid & 31, ty = tid >> 5;          // 32 x 8
        __shared__ float t[32][33];
        #pragma unroll
        for (int jj = 0; jj < 4; jj++) {
            int k = k0 + ty + jj * 8;
            float r = raw[k * Dn + d0 + tx];
            t[ty + jj * 8][tx] = fmaxf(r, 0.0f) + __logf(1.0f + __expf(-fabsf(r)));
        }
        __syncthreads();
        #pragma unroll
        for (int jj = 0; jj < 4; jj++) {
            int d = d0 + ty + jj * 8;
            g_wt[d * Kn + k0 + tx] = __float2bfloat16(t[tx][ty + jj * 8]);
        }
    }

    gridbar(NCTA);                 // prep complete everywhere

    // ================= Phase 1: G1 (dist -> rbf, + nz detect) =============
    gemm_tile<false>(sm, (c & 31) * 64, (c >> 5) * 64, nullptr);

    gridbar(2 * NCTA);             // rbf + g_anynz final everywhere

    const unsigned anynz = *(volatile unsigned*)&g_anynz;

    // ================= Phase 2: G2 (zero fast-path / full fallback) ========
    if (anynz) {
        #pragma unroll
        for (int tt = 0; tt < 2; tt++) {
            const int tile = c + tt * NCTA;
            gemm_tile<true>(sm, (tile & 31) * 64, (tile >> 5) * 64, out);
        }
    } else {
        // rbf == 0 everywhere -> h == 0 -> out = 1/(0+eps) exactly.
        const float v = __fdividef(1.0f, 0.0f + 1e-3f);
        const float4 fv = make_float4(v, v, v, v);
        #pragma unroll
        for (int tt = 0; tt < 2; tt++) {
            const int tile = c + tt * NCTA;
            const int m0 = (tile & 31) * 64, n0 = (tile >> 5) * 64;
            const int r = m0 + (tid >> 2);
            float4* dst = (float4*)(out + (size_t)r * Dn + n0 + (tid & 3) * 16);
            dst[0] = fv;  dst[1] = fv;  dst[2] = fv;  dst[3] = fv;
        }
    }

    // -------- reset barrier + flag state for next replay --------------------
    __syncthreads();
    if (tid == 0) {
        unsigned dn = atomicAdd(&g_done, 1u);
        if (dn == NCTA - 1u) {
            g_count = 0u;
            g_done  = 0u;
            g_anynz = 0u;
            __threadfence();
        }
    }
}

// ---------------------------------------------------------------------------
extern "C" void kernel_launch(void* const* d_in, const int* in_sizes, int n_in,
                              void* d_out, int out_size) {
    const float* x           = (const float*)d_in[0];
    const float* centers     = (const float*)d_in[1];
    const float* bandwidths  = (const float*)d_in[2];
    const float* raw_weights = (const float*)d_in[3];
    float* out = (float*)d_out;

    static bool attr_set = false;
    if (!attr_set) {
        cudaFuncSetAttribute(mega_kern,
                             cudaFuncAttributeMaxDynamicSharedMemorySize, SMEMSZ);
        attr_set = true;
    }

    mega_kern<<<NCTA, 256, SMEMSZ>>>(x, centers, bandwidths, raw_weights, out);
}

// round 16
// speedup vs baseline: 1.0017x; 1.0017x over previous
#include <cuda_runtime.h>
#include <cuda_bf16.h>
#include <cstdint>
#include <math.h>

// Problem shape (fixed by setup_inputs)
#define Bn 2048
#define Kn 256
#define Dn 512
#define NCTA 256        // fuse grid: 256 CTAs (2 co-resident/SM; barrier-safe)

// bf16 staging buffers (__device__ globals: allocation-free)
__device__ __nv_bfloat16 g_abig[Bn * 1024];  // [b][ x^2(512) | x(512) ]
__device__ __nv_bfloat16 g_bmat[Kn * 1024];  // [k][ bw(512) | -2bw*c(512) ]
__device__ __nv_bfloat16 g_rbf [Bn * Kn];    // rbf, K-major
__device__ __nv_bfloat16 g_wt  [Dn * Kn];    // softplus(W)^T: [d][k]
__device__ float         g_ck  [Kn];         // sum_d bw*c^2
__device__ unsigned g_count, g_done, g_anynz; // barrier + sparsity flag

// ---------------------------------------------------------------------------
// Helpers (arch-generic: ldmatrix / mma.sync / cp.async — NO tcgen05)
// ---------------------------------------------------------------------------
__device__ __forceinline__ uint32_t s2u(const void* p) {
    uint32_t a;
    asm("{ .reg .u64 t; cvta.to.shared.u64 t, %1; cvt.u32.u64 %0, t; }"
        : "=r"(a) : "l"(p));
    return a;
}
#define SW128(o) ((o) ^ (((o) >> 3) & 0x70))

__device__ __forceinline__ void cp16(uint32_t s, const void* g) {
    asm volatile("cp.async.cg.shared.global [%0], [%1], 16;" :: "r"(s), "l"(g));
}

__device__ __forceinline__ void ldsm4(uint32_t* r, uint32_t addr) {
    asm volatile("ldmatrix.sync.aligned.m8n8.x4.shared.b16 {%0,%1,%2,%3}, [%4];"
                 : "=r"(r[0]), "=r"(r[1]), "=r"(r[2]), "=r"(r[3]) : "r"(addr));
}

__device__ __forceinline__ void mma16816(float* c, const uint32_t* a, const uint32_t* b) {
    asm volatile(
        "mma.sync.aligned.m16n8k16.row.col.f32.bf16.bf16.f32 "
        "{%0,%1,%2,%3}, {%4,%5,%6,%7}, {%8,%9}, {%0,%1,%2,%3};"
        : "+f"(c[0]), "+f"(c[1]), "+f"(c[2]), "+f"(c[3])
        : "r"(a[0]), "r"(a[1]), "r"(a[2]), "r"(a[3]), "r"(b[0]), "r"(b[1]));
}

__device__ __forceinline__ uint32_t bits2(__nv_bfloat162 v) {
    return *(uint32_t*)&v;
}

__device__ __forceinline__ void gridbar(unsigned target) {
    __threadfence();
    __syncthreads();
    if (threadIdx.x == 0) {
        atomicAdd(&g_count, 1u);
        while (atomicAdd(&g_count, 0u) < target) { }
    }
    __syncthreads();
    __threadfence();
}

// ---------------------------------------------------------------------------
// Fused prep (R11/R14 known-good): 416 blocks x 256 threads.
// ---------------------------------------------------------------------------
__global__ void __launch_bounds__(256)
prep_all(const float* __restrict__ x, const float* __restrict__ centers,
         const float* __restrict__ bandwidths, const float* __restrict__ raw) {
    const int bid = blockIdx.x, tid = threadIdx.x;

    if (bid < 256) {                         // ---- prepA ----
        const int e = (bid * 256 + tid) * 16;
        const int row = e >> 9;
        const int d = e & 511;
        const float4* src = (const float4*)(x + e);
        float4 v0 = src[0], v1 = src[1], v2 = src[2], v3 = src[3];
        uint4 sq0, sq1, xx0, xx1;
        sq0.x = bits2(__floats2bfloat162_rn(v0.x * v0.x, v0.y * v0.y));
        sq0.y = bits2(__floats2bfloat162_rn(v0.z * v0.z, v0.w * v0.w));
        sq0.z = bits2(__floats2bfloat162_rn(v1.x * v1.x, v1.y * v1.y));
        sq0.w = bits2(__floats2bfloat162_rn(v1.z * v1.z, v1.w * v1.w));
        sq1.x = bits2(__floats2bfloat162_rn(v2.x * v2.x, v2.y * v2.y));
        sq1.y = bits2(__floats2bfloat162_rn(v2.z * v2.z, v2.w * v2.w));
        sq1.z = bits2(__floats2bfloat162_rn(v3.x * v3.x, v3.y * v3.y));
        sq1.w = bits2(__floats2bfloat162_rn(v3.z * v3.z, v3.w * v3.w));
        xx0.x = bits2(__floats2bfloat162_rn(v0.x, v0.y));
        xx0.y = bits2(__floats2bfloat162_rn(v0.z, v0.w));
        xx0.z = bits2(__floats2bfloat162_rn(v1.x, v1.y));
        xx0.w = bits2(__floats2bfloat162_rn(v1.z, v1.w));
        xx1.x = bits2(__floats2bfloat162_rn(v2.x, v2.y));
        xx1.y = bits2(__floats2bfloat162_rn(v2.z, v2.w));
        xx1.z = bits2(__floats2bfloat162_rn(v3.x, v3.y));
        xx1.w = bits2(__floats2bfloat162_rn(v3.z, v3.w));
        uint4* dsq = (uint4*)&g_abig[row * 1024 + d];
        uint4* dxx = (uint4*)&g_abig[row * 1024 + 512 + d];
        dsq[0] = sq0;  dsq[1] = sq1;
        dxx[0] = xx0;  dxx[1] = xx1;
        return;
    }

    if (bid < 288) {                         // ---- prepB + ck ----
        const int e = ((bid - 256) * 256 + tid) * 16;
        const int k = e >> 9;
        const int d = e & 511;
        const float4* sb = (const float4*)(bandwidths + e);
        const float4* sc = (const float4*)(centers + e);
        float4 b0 = sb[0], b1 = sb[1], b2 = sb[2], b3 = sb[3];
        float4 c0 = sc[0], c1 = sc[1], c2 = sc[2], c3 = sc[3];
        uint4 wb0, wb1, wc0, wc1;
        wb0.x = bits2(__floats2bfloat162_rn(b0.x, b0.y));
        wb0.y = bits2(__floats2bfloat162_rn(b0.z, b0.w));
        wb0.z = bits2(__floats2bfloat162_rn(b1.x, b1.y));
        wb0.w = bits2(__floats2bfloat162_rn(b1.z, b1.w));
        wb1.x = bits2(__floats2bfloat162_rn(b2.x, b2.y));
        wb1.y = bits2(__floats2bfloat162_rn(b2.z, b2.w));
        wb1.z = bits2(__floats2bfloat162_rn(b3.x, b3.y));
        wb1.w = bits2(__floats2bfloat162_rn(b3.z, b3.w));
        wc0.x = bits2(__floats2bfloat162_rn(-2.0f * b0.x * c0.x, -2.0f * b0.y * c0.y));
        wc0.y = bits2(__floats2bfloat162_rn(-2.0f * b0.z * c0.z, -2.0f * b0.w * c0.w));
        wc0.z = bits2(__floats2bfloat162_rn(-2.0f * b1.x * c1.x, -2.0f * b1.y * c1.y));
        wc0.w = bits2(__floats2bfloat162_rn(-2.0f * b1.z * c1.z, -2.0f * b1.w * c1.w));
        wc1.x = bits2(__floats2bfloat162_rn(-2.0f * b2.x * c2.x, -2.0f * b2.y * c2.y));
        wc1.y = bits2(__floats2bfloat162_rn(-2.0f * b2.z * c2.z, -2.0f * b2.w * c2.w));
        wc1.z = bits2(__floats2bfloat162_rn(-2.0f * b3.x * c3.x, -2.0f * b3.y * c3.y));
        wc1.w = bits2(__floats2bfloat162_rn(-2.0f * b3.z * c3.z, -2.0f * b3.w * c3.w));
        uint4* db = (uint4*)&g_bmat[k * 1024 + d];
        uint4* dc = (uint4*)&g_bmat[k * 1024 + 512 + d];
        db[0] = wb0;  db[1] = wb1;
        dc[0] = wc0;  dc[1] = wc1;
        float s = b0.x * c0.x * c0.x + b0.y * c0.y * c0.y
                + b0.z * c0.z * c0.z + b0.w * c0.w * c0.w
                + b1.x * c1.x * c1.x + b1.y * c1.y * c1.y
                + b1.z * c1.z * c1.z + b1.w * c1.w * c1.w
                + b2.x * c2.x * c2.x + b2.y * c2.y * c2.y
                + b2.z * c2.z * c2.z + b2.w * c2.w * c2.w
                + b3.x * c3.x * c3.x + b3.y * c3.y * c3.y
                + b3.z * c3.z * c3.z + b3.w * c3.w * c3.w;
        #pragma unroll
        for (int o = 16; o > 0; o >>= 1)
            s += __shfl_down_sync(0xffffffffu, s, o);
        if ((tid & 31) == 0) g_ck[k] = s;
        return;
    }

    {                                        // ---- prepW ----
        const int t2 = bid - 288;
        const int d0 = (t2 & 15) * 32, k0 = (t2 >> 4) * 32;
        const int tx = tid & 31, ty = tid >> 5;          // 32 x 8
        __shared__ float t[32][33];
        #pragma unroll
        for (int jj = 0; jj < 4; jj++) {
            int k = k0 + ty + jj * 8;
            float r = raw[k * Dn + d0 + tx];
            t[ty + jj * 8][tx] = fmaxf(r, 0.0f) + __logf(1.0f + __expf(-fabsf(r)));
        }
        __syncthreads();
        #pragma unroll
        for (int jj = 0; jj < 4; jj++) {
            int d = d0 + ty + jj * 8;
            g_wt[d * Kn + k0 + tx] = __float2bfloat16(t[tx][ty + jj * 8]);
        }
    }
}

#define G1_STAGE 12288          // A 4KB + B 8KB
#define G2_STAGE 16384
#define SMEMSZ (6 * G1_STAGE)   // 73728 (covers G2's 4 x 16KB = 64KB too)

// ---------------------------------------------------------------------------
// G1 tile: dist[32,64] = A[32,1024] x B[64,1024]^T, split-K 2 warp groups,
// warp tile 16x32, 6-stage pipeline. Raises g_anynz if any rbf != 0.
// ---------------------------------------------------------------------------
__device__ __forceinline__ void g1_tile(char* sm, int m0, int n0) {
    const uint32_t T0 = s2u(sm);
    const int tid = threadIdx.x, wid = tid >> 5, l = tid & 31;
    const int grp = wid >> 2, wg = wid & 3;
    const int wm = wg & 1, wn = wg >> 1;

    const int lr = l & 7, sel = l >> 3;
    const int a_row = wm * 16 + (sel & 1) * 8 + lr;
    const uint32_t a_kb = (uint32_t)((sel >> 1) * 16);
    const int b_row = wn * 32 + (sel >> 1) * 8 + lr;
    const uint32_t b_kb = (uint32_t)((sel & 1) * 16);

    __syncthreads();

    #define LOAD_CHUNK(ch) do {                                              \
        uint32_t _sa = T0 + ((ch) % 6) * G1_STAGE;                           \
        const __nv_bfloat16* _ga = g_abig + (size_t)m0 * 1024 + (ch) * 64;   \
        const __nv_bfloat16* _gb = g_bmat + (size_t)n0 * 1024 + (ch) * 64;   \
        {   /* A: 32 rows x 8 segs = 256 units, 1 per thread */              \
            int r = tid >> 3, cc = tid & 7;                                  \
            cp16(_sa + SW128((uint32_t)(r * 128 + cc * 16)),                 \
                 _ga + (size_t)r * 1024 + cc * 8);                           \
        }                                                                    \
        _Pragma("unroll")                                                    \
        for (int q = 0; q < 2; q++) {   /* B: 64 rows = 512 units */         \
            int u = tid + q * 256;                                           \
            int r = u >> 3, cc = u & 7;                                      \
            cp16(_sa + 4096 + SW128((uint32_t)(r * 128 + cc * 16)),          \
                 _gb + (size_t)r * 1024 + cc * 8);                           \
        }                                                                    \
    } while (0)

    #define LOAD_PAIR(p) do {                                                \
        LOAD_CHUNK(2 * (p));  LOAD_CHUNK(2 * (p) + 1);                       \
        asm volatile("cp.async.commit_group;");                              \
    } while (0)

    #define LDFRAG(sa, sbb, ks, buf) do {                                    \
        ldsm4(af[buf], (sa) + SW128((uint32_t)(a_row * 128)                  \
                                    + (uint32_t)((ks) * 32) + a_kb));        \
        _Pragma("unroll")                                                    \
        for (int bi = 0; bi < 2; bi++)                                       \
            ldsm4(bf[buf][bi], (sbb) + SW128((uint32_t)((b_row + bi * 16) * 128) \
                                             + (uint32_t)((ks) * 32) + b_kb)); \
    } while (0)

    float acc[4][4];
    #pragma unroll
    for (int nj = 0; nj < 4; nj++)
        #pragma unroll
        for (int e = 0; e < 4; e++) acc[nj][e] = 0.0f;

    LOAD_PAIR(0);
    LOAD_PAIR(1);

    uint32_t af[2][4], bf[2][2][4];

    for (int t = 0; t < 8; t++) {
        if (t < 7) asm volatile("cp.async.wait_group 1;");
        else       asm volatile("cp.async.wait_group 0;");
        __syncthreads();
        if (t + 2 < 8) LOAD_PAIR(t + 2);

        const int ch = 2 * t + grp;
        const uint32_t sa  = T0 + (ch % 6) * G1_STAGE;
        const uint32_t sbb = sa + 4096;

        LDFRAG(sa, sbb, 0, 0);
        #pragma unroll
        for (int ks = 0; ks < 4; ks++) {
            const int cur = ks & 1;
            if (ks < 3) LDFRAG(sa, sbb, ks + 1, cur ^ 1);
            #pragma unroll
            for (int nj = 0; nj < 4; nj++)
                mma16816(acc[nj], af[cur], &bf[cur][nj >> 1][(nj & 1) * 2]);
        }
    }
    #undef LDFRAG
    #undef LOAD_PAIR
    #undef LOAD_CHUNK

    // ---- cross-group reduce (Rb pitch 72, 32 rows) ------------------------
    float* Rb = (float*)sm;
    const int rrow = wm * 16 + (l >> 2);
    const int rcol = wn * 32 + 2 * (l & 3);
    __syncthreads();
    if (grp == 1) {
        #pragma unroll
        for (int nj = 0; nj < 4; nj++) {
            const int c2 = rcol + nj * 8;
            *(float2*)&Rb[rrow * 72 + c2]       = make_float2(acc[nj][0], acc[nj][1]);
            *(float2*)&Rb[(rrow + 8) * 72 + c2] = make_float2(acc[nj][2], acc[nj][3]);
        }
    }
    __syncthreads();

    int nzpred = 0;
    if (grp == 0) {
        #pragma unroll
        for (int nj = 0; nj < 4; nj++) {
            const int c2 = rcol + nj * 8;
            float2 p0 = *(const float2*)&Rb[rrow * 72 + c2];
            float2 p1 = *(const float2*)&Rb[(rrow + 8) * 72 + c2];
            acc[nj][0] += p0.x;  acc[nj][1] += p0.y;
            acc[nj][2] += p1.x;  acc[nj][3] += p1.y;
        }
        const int erow = m0 + rrow;
        #pragma unroll
        for (int nj = 0; nj < 4; nj++) {
            const int col = rcol + nj * 8;
            const float ck0 = g_ck[n0 + col];
            const float ck1 = g_ck[n0 + col + 1];
            float v0 = __expf(-0.5f * (acc[nj][0] + ck0));
            float v1 = __expf(-0.5f * (acc[nj][1] + ck1));
            float v2 = __expf(-0.5f * (acc[nj][2] + ck0));
            float v3 = __expf(-0.5f * (acc[nj][3] + ck1));
            nzpred |= (v0 != 0.0f) | (v1 != 0.0f) | (v2 != 0.0f) | (v3 != 0.0f);
            __nv_bfloat162 p0 = __floats2bfloat162_rn(v0, v1);
            __nv_bfloat162 p1 = __floats2bfloat162_rn(v2, v3);
            *(__nv_bfloat162*)&g_rbf[(size_t)erow * Kn + n0 + col]       = p0;
            *(__nv_bfloat162*)&g_rbf[(size_t)(erow + 8) * Kn + n0 + col] = p1;
        }
    }

    int any = __syncthreads_or(nzpred);
    if (any && tid == 0) atomicOr(&g_anynz, 1u);
    __syncthreads();
}

// ---------------------------------------------------------------------------
// G2 tile (R14 known-good 64x64, split-K 2 groups, 4 stages of 16KB).
// ---------------------------------------------------------------------------
__device__ __forceinline__ void g2_tile(char* sm, int m0, int n0,
                                        float* __restrict__ out) {
    const uint32_t T0 = s2u(sm);
    const int tid = threadIdx.x, wid = tid >> 5, l = tid & 31;
    const int grp = wid >> 2, wg = wid & 3;
    const int wm = wg & 1, wn = wg >> 1;

    const int lr = l & 7, sel = l >> 3;
    const int a_row = wm * 32 + (sel & 1) * 8 + lr;
    const uint32_t a_kb = (uint32_t)((sel >> 1) * 16);
    const int b_row = wn * 32 + (sel >> 1) * 8 + lr;
    const uint32_t b_kb = (uint32_t)((sel & 1) * 16);

    __syncthreads();

    #define LOAD_CHUNK2(ch) do {                                             \
        uint32_t _sa = T0 + ((ch) & 3) * G2_STAGE;                           \
        const __nv_bfloat16* _ga = g_rbf + (size_t)m0 * 256 + (ch) * 64;     \
        const __nv_bfloat16* _gb = g_wt  + (size_t)n0 * 256 + (ch) * 64;     \
        _Pragma("unroll")                                                    \
        for (int q = 0; q < 2; q++) {                                        \
            int u = tid + q * 256;                                           \
            int r = u >> 3, cc = u & 7;                                      \
            uint32_t off = SW128((uint32_t)(r * 128 + cc * 16));             \
            cp16(_sa        + off, _ga + (size_t)r * 256 + cc * 8);          \
            cp16(_sa + 8192 + off, _gb + (size_t)r * 256 + cc * 8);          \
        }                                                                    \
    } while (0)

    float acc[2][4][4];
    #pragma unroll
    for (int mi = 0; mi < 2; mi++)
        #pragma unroll
        for (int nj = 0; nj < 4; nj++)
            #pragma unroll
            for (int e = 0; e < 4; e++) acc[mi][nj][e] = 0.0f;

    LOAD_CHUNK2(0);  LOAD_CHUNK2(1);
    asm volatile("cp.async.commit_group;");
    LOAD_CHUNK2(2);  LOAD_CHUNK2(3);
    asm volatile("cp.async.commit_group;");

    uint32_t af[2][2][4], bf[2][2][4];

    #define LDFRAG2(sa, sbb, ks, buf) do {                                   \
        _Pragma("unroll")                                                    \
        for (int mi = 0; mi < 2; mi++)                                       \
            ldsm4(af[buf][mi], (sa) + SW128((uint32_t)((a_row + mi * 16) * 128) \
                                            + (uint32_t)((ks) * 32) + a_kb)); \
        _Pragma("unroll")                                                    \
        for (int bi = 0; bi < 2; bi++)                                       \
            ldsm4(bf[buf][bi], (sbb) + SW128((uint32_t)((b_row + bi * 16) * 128) \
                                             + (uint32_t)((ks) * 32) + b_kb)); \
    } while (0)

    for (int t = 0; t < 2; t++) {
        if (t == 0) asm volatile("cp.async.wait_group 1;");
        else        asm volatile("cp.async.wait_group 0;");
        __syncthreads();
        const int ch = 2 * t + grp;
        const uint32_t sa  = T0 + (ch & 3) * G2_STAGE;
        const uint32_t sbb = sa + 8192;
        LDFRAG2(sa, sbb, 0, 0);
        #pragma unroll
        for (int ks = 0; ks < 4; ks++) {
            const int cur = ks & 1;
            if (ks < 3) LDFRAG2(sa, sbb, ks + 1, cur ^ 1);
            #pragma unroll
            for (int mi = 0; mi < 2; mi++)
                #pragma unroll
                for (int nj = 0; nj < 4; nj++)
                    mma16816(acc[mi][nj], af[cur][mi], &bf[cur][nj >> 1][(nj & 1) * 2]);
        }
    }
    #undef LDFRAG2
    #undef LOAD_CHUNK2

    float* Rb = (float*)sm;
    const int rrow = wm * 32 + (l >> 2);
    const int rcol = wn * 32 + 2 * (l & 3);
    __syncthreads();
    if (grp == 1) {
        #pragma unroll
        for (int mi = 0; mi < 2; mi++)
            #pragma unroll
            for (int nj = 0; nj < 4; nj++) {
                const int r = rrow + mi * 16, c2 = rcol + nj * 8;
                *(float2*)&Rb[r * 72 + c2]       = make_float2(acc[mi][nj][0], acc[mi][nj][1]);
                *(float2*)&Rb[(r + 8) * 72 + c2] = make_float2(acc[mi][nj][2], acc[mi][nj][3]);
            }
    }
    __syncthreads();
    if (grp == 0) {
        const float eps = 1e-3f;
        #pragma unroll
        for (int mi = 0; mi < 2; mi++)
            #pragma unroll
            for (int nj = 0; nj < 4; nj++) {
                const int r = rrow + mi * 16, c2 = rcol + nj * 8;
                float2 p0 = *(const float2*)&Rb[r * 72 + c2];
                float2 p1 = *(const float2*)&Rb[(r + 8) * 72 + c2];
                const int col = n0 + c2;
                const int gr = m0 + r;
                float2 o0, o1;
                o0.x = __fdividef(1.0f, acc[mi][nj][0] + p0.x + eps);
                o0.y = __fdividef(1.0f, acc[mi][nj][1] + p0.y + eps);
                o1.x = __fdividef(1.0f, acc[mi][nj][2] + p1.x + eps);
                o1.y = __fdividef(1.0f, acc[mi][nj][3] + p1.y + eps);
                *(float2*)(out + (size_t)gr * Dn + col)       = o0;
                *(float2*)(out + (size_t)(gr + 8) * Dn + col) = o1;
            }
    }
    __syncthreads();
}

// ---------------------------------------------------------------------------
// fuse_kern: G1 (256 small tiles) -> gridbar -> G2 (zero fast-path / full).
// ---------------------------------------------------------------------------
__global__ void __launch_bounds__(256, 1)
fuse_kern(float* __restrict__ out) {
    extern __shared__ char sm[];
    const int c = blockIdx.x, tid = threadIdx.x;

    // G1: 256 tiles = 64 m-blocks(32) x 4 k-blocks(64)
    g1_tile(sm, (c & 63) * 32, (c >> 6) * 64);

    gridbar(NCTA);     // rbf + g_anynz final everywhere

    const unsigned anynz = *(volatile unsigned*)&g_anynz;

    // G2: 256 tiles = 32 m-blocks(64) x 8 d-blocks(64), 1 per CTA
    if (anynz) {
        g2_tile(sm, (c & 31) * 64, (c >> 5) * 64, out);
    } else {
        // rbf == 0 everywhere -> h == 0 -> out = 1/(0+eps) exactly.
        const float v = __fdividef(1.0f, 0.0f + 1e-3f);
        const float4 fv = make_float4(v, v, v, v);
        const int m0 = (c & 31) * 64, n0 = (c >> 5) * 64;
        const int r = m0 + (tid >> 2);
        float4* dst = (float4*)(out + (size_t)r * Dn + n0 + (tid & 3) * 16);
        dst[0] = fv;  dst[1] = fv;  dst[2] = fv;  dst[3] = fv;
    }

    // reset barrier + flag state for next replay
    __syncthreads();
    if (tid == 0) {
        unsigned dn = atomicAdd(&g_done, 1u);
        if (dn == NCTA - 1u) {
            g_count = 0u;
            g_done  = 0u;
            g_anynz = 0u;
            __threadfence();
        }
    }
}

// ---------------------------------------------------------------------------
extern "C" void kernel_launch(void* const* d_in, const int* in_sizes, int n_in,
                              void* d_out, int out_size) {
    const float* x           = (const float*)d_in[0];
    const float* centers     = (const float*)d_in[1];
    const float* bandwidths  = (const float*)d_in[2];
    const float* raw_weights = (const float*)d_in[3];
    float* out = (float*)d_out;

    static bool attr_set = false;
    if (!attr_set) {
        cudaFuncSetAttribute(fuse_kern,
                             cudaFuncAttributeMaxDynamicSharedMemorySize, SMEMSZ);
        attr_set = true;
    }

    prep_all<<<416, 256>>>(x, centers, bandwidths, raw_weights);
    fuse_kern<<<NCTA, 256, SMEMSZ>>>(out);
}

// round 17
// speedup vs baseline: 1.1191x; 1.1172x over previous
#include <cuda_runtime.h>
#include <cuda_bf16.h>
#include <cstdint>
#include <math.h>

// Problem shape (fixed by setup_inputs)
#define Bn 2048
#define Kn 256
#define Dn 512
#define NCTA 128        // fuse grid; all co-resident (96KB smem, <= #SMs)

// bf16 staging buffers (__device__ globals: allocation-free)
__device__ __nv_bfloat16 g_abig[Bn * 1024];  // [b][ x^2(512) | x(512) ]
__device__ __nv_bfloat16 g_bmat[Kn * 1024];  // [k][ bw(512) | -2bw*c(512) ]
__device__ __nv_bfloat16 g_rbf [Bn * Kn];    // rbf, K-major
__device__ __nv_bfloat16 g_wt  [Dn * Kn];    // softplus(W)^T: [d][k]
__device__ float         g_ck  [Kn];         // sum_d bw*c^2
// per-m-panel sync state (32 panels x 4 CTAs); self-resetting
__device__ unsigned g_pcnt[32], g_pnz[32], g_pdone[32];

// exp(-0.5*d) == 0 in fp32 (incl. denormals) whenever d >= 208
// (0.5*208 = 104 > -ln(2^-149) = 103.28). Conservative: values below the
// threshold always go through the exact exp path.
#define DIST_ZERO_THRESH 208.0f

// ---------------------------------------------------------------------------
// Helpers (arch-generic: ldmatrix / mma.sync / cp.async — NO tcgen05)
// ---------------------------------------------------------------------------
__device__ __forceinline__ uint32_t s2u(const void* p) {
    uint32_t a;
    asm("{ .reg .u64 t; cvta.to.shared.u64 t, %1; cvt.u32.u64 %0, t; }"
        : "=r"(a) : "l"(p));
    return a;
}
#define SW128(o) ((o) ^ (((o) >> 3) & 0x70))

__device__ __forceinline__ void cp16(uint32_t s, const void* g) {
    asm volatile("cp.async.cg.shared.global [%0], [%1], 16;" :: "r"(s), "l"(g));
}

__device__ __forceinline__ void ldsm4(uint32_t* r, uint32_t addr) {
    asm volatile("ldmatrix.sync.aligned.m8n8.x4.shared.b16 {%0,%1,%2,%3}, [%4];"
                 : "=r"(r[0]), "=r"(r[1]), "=r"(r[2]), "=r"(r[3]) : "r"(addr));
}

__device__ __forceinline__ void mma16816(float* c, const uint32_t* a, const uint32_t* b) {
    asm volatile(
        "mma.sync.aligned.m16n8k16.row.col.f32.bf16.bf16.f32 "
        "{%0,%1,%2,%3}, {%4,%5,%6,%7}, {%8,%9}, {%0,%1,%2,%3};"
        : "+f"(c[0]), "+f"(c[1]), "+f"(c[2]), "+f"(c[3])
        : "r"(a[0]), "r"(a[1]), "r"(a[2]), "r"(a[3]), "r"(b[0]), "r"(b[1]));
}

__device__ __forceinline__ uint32_t bits2(__nv_bfloat162 v) {
    return *(uint32_t*)&v;
}

// ---------------------------------------------------------------------------
// Fused prep (R11/R14 known-good): 416 blocks x 256 threads.
// ---------------------------------------------------------------------------
__global__ void __launch_bounds__(256)
prep_all(const float* __restrict__ x, const float* __restrict__ centers,
         const float* __restrict__ bandwidths, const float* __restrict__ raw) {
    const int bid = blockIdx.x, tid = threadIdx.x;

    if (bid < 256) {                         // ---- prepA ----
        const int e = (bid * 256 + tid) * 16;
        const int row = e >> 9;
        const int d = e & 511;
        const float4* src = (const float4*)(x + e);
        float4 v0 = src[0], v1 = src[1], v2 = src[2], v3 = src[3];
        uint4 sq0, sq1, xx0, xx1;
        sq0.x = bits2(__floats2bfloat162_rn(v0.x * v0.x, v0.y * v0.y));
        sq0.y = bits2(__floats2bfloat162_rn(v0.z * v0.z, v0.w * v0.w));
        sq0.z = bits2(__floats2bfloat162_rn(v1.x * v1.x, v1.y * v1.y));
        sq0.w = bits2(__floats2bfloat162_rn(v1.z * v1.z, v1.w * v1.w));
        sq1.x = bits2(__floats2bfloat162_rn(v2.x * v2.x, v2.y * v2.y));
        sq1.y = bits2(__floats2bfloat162_rn(v2.z * v2.z, v2.w * v2.w));
        sq1.z = bits2(__floats2bfloat162_rn(v3.x * v3.x, v3.y * v3.y));
        sq1.w = bits2(__floats2bfloat162_rn(v3.z * v3.z, v3.w * v3.w));
        xx0.x = bits2(__floats2bfloat162_rn(v0.x, v0.y));
        xx0.y = bits2(__floats2bfloat162_rn(v0.z, v0.w));
        xx0.z = bits2(__floats2bfloat162_rn(v1.x, v1.y));
        xx0.w = bits2(__floats2bfloat162_rn(v1.z, v1.w));
        xx1.x = bits2(__floats2bfloat162_rn(v2.x, v2.y));
        xx1.y = bits2(__floats2bfloat162_rn(v2.z, v2.w));
        xx1.z = bits2(__floats2bfloat162_rn(v3.x, v3.y));
        xx1.w = bits2(__floats2bfloat162_rn(v3.z, v3.w));
        uint4* dsq = (uint4*)&g_abig[row * 1024 + d];
        uint4* dxx = (uint4*)&g_abig[row * 1024 + 512 + d];
        dsq[0] = sq0;  dsq[1] = sq1;
        dxx[0] = xx0;  dxx[1] = xx1;
        return;
    }

    if (bid < 288) {                         // ---- prepB + ck ----
        const int e = ((bid - 256) * 256 + tid) * 16;
        const int k = e >> 9;
        const int d = e & 511;
        const float4* sb = (const float4*)(bandwidths + e);
        const float4* sc = (const float4*)(centers + e);
        float4 b0 = sb[0], b1 = sb[1], b2 = sb[2], b3 = sb[3];
        float4 c0 = sc[0], c1 = sc[1], c2 = sc[2], c3 = sc[3];
        uint4 wb0, wb1, wc0, wc1;
        wb0.x = bits2(__floats2bfloat162_rn(b0.x, b0.y));
        wb0.y = bits2(__floats2bfloat162_rn(b0.z, b0.w));
        wb0.z = bits2(__floats2bfloat162_rn(b1.x, b1.y));
        wb0.w = bits2(__floats2bfloat162_rn(b1.z, b1.w));
        wb1.x = bits2(__floats2bfloat162_rn(b2.x, b2.y));
        wb1.y = bits2(__floats2bfloat162_rn(b2.z, b2.w));
        wb1.z = bits2(__floats2bfloat162_rn(b3.x, b3.y));
        wb1.w = bits2(__floats2bfloat162_rn(b3.z, b3.w));
        wc0.x = bits2(__floats2bfloat162_rn(-2.0f * b0.x * c0.x, -2.0f * b0.y * c0.y));
        wc0.y = bits2(__floats2bfloat162_rn(-2.0f * b0.z * c0.z, -2.0f * b0.w * c0.w));
        wc0.z = bits2(__floats2bfloat162_rn(-2.0f * b1.x * c1.x, -2.0f * b1.y * c1.y));
        wc0.w = bits2(__floats2bfloat162_rn(-2.0f * b1.z * c1.z, -2.0f * b1.w * c1.w));
        wc1.x = bits2(__floats2bfloat162_rn(-2.0f * b2.x * c2.x, -2.0f * b2.y * c2.y));
        wc1.y = bits2(__floats2bfloat162_rn(-2.0f * b2.z * c2.z, -2.0f * b2.w * c2.w));
        wc1.z = bits2(__floats2bfloat162_rn(-2.0f * b3.x * c3.x, -2.0f * b3.y * c3.y));
        wc1.w = bits2(__floats2bfloat162_rn(-2.0f * b3.z * c3.z, -2.0f * b3.w * c3.w));
        uint4* db = (uint4*)&g_bmat[k * 1024 + d];
        uint4* dc = (uint4*)&g_bmat[k * 1024 + 512 + d];
        db[0] = wb0;  db[1] = wb1;
        dc[0] = wc0;  dc[1] = wc1;
        float s = b0.x * c0.x * c0.x + b0.y * c0.y * c0.y
                + b0.z * c0.z * c0.z + b0.w * c0.w * c0.w
                + b1.x * c1.x * c1.x + b1.y * c1.y * c1.y
                + b1.z * c1.z * c1.z + b1.w * c1.w * c1.w
                + b2.x * c2.x * c2.x + b2.y * c2.y * c2.y
                + b2.z * c2.z * c2.z + b2.w * c2.w * c2.w
                + b3.x * c3.x * c3.x + b3.y * c3.y * c3.y
                + b3.z * c3.z * c3.z + b3.w * c3.w * c3.w;
        #pragma unroll
        for (int o = 16; o > 0; o >>= 1)
            s += __shfl_down_sync(0xffffffffu, s, o);
        if ((tid & 31) == 0) g_ck[k] = s;
        return;
    }

    {                                        // ---- prepW ----
        const int t2 = bid - 288;
        const int d0 = (t2 & 15) * 32, k0 = (t2 >> 4) * 32;
        const int tx = tid & 31, ty = tid >> 5;          // 32 x 8
        __shared__ float t[32][33];
        #pragma unroll
        for (int jj = 0; jj < 4; jj++) {
            int k = k0 + ty + jj * 8;
            float r = raw[k * Dn + d0 + tx];
            t[ty + jj * 8][tx] = fmaxf(r, 0.0f) + __logf(1.0f + __expf(-fabsf(r)));
        }
        __syncthreads();
        #pragma unroll
        for (int jj = 0; jj < 4; jj++) {
            int d = d0 + ty + jj * 8;
            g_wt[d * Kn + k0 + tx] = __float2bfloat16(t[tx][ty + jj * 8]);
        }
    }
}

// ---------------------------------------------------------------------------
// GEMM tile body (R14 known-good: split-K 2 warp-groups, register-pipelined
// fragments). G1 path: dist-threshold nz test; returns tile_nz (uniform).
// ---------------------------------------------------------------------------
#define STAGE_BYTES 16384
#define NSTAGE 6
#define SMEMSZ (NSTAGE * STAGE_BYTES)   // 98304 (G2 path uses first 4 stages)

template<bool ISG2>
__device__ __forceinline__ int gemm_tile(char* sm, int m0, int n0,
                                         float* __restrict__ out) {
    constexpr int LD     = ISG2 ? 256 : 1024;
    constexpr int NCHUNK = ISG2 ? 4   : 16;
    constexpr int NSTEP  = NCHUNK / 2;
    constexpr int NST    = ISG2 ? 4 : 6;
    const __nv_bfloat16* __restrict__ A  = ISG2 ? g_rbf : g_abig;
    const __nv_bfloat16* __restrict__ Bm = ISG2 ? g_wt  : g_bmat;

    const uint32_t T0 = s2u(sm);
    const int tid = threadIdx.x, wid = tid >> 5, l = tid & 31;
    const int grp = wid >> 2, wg = wid & 3;
    const int wm = wg & 1, wn = wg >> 1;

    const int lr = l & 7, sel = l >> 3;
    const int a_row = wm * 32 + (sel & 1) * 8 + lr;
    const uint32_t a_kb = (uint32_t)((sel >> 1) * 16);
    const int b_row = wn * 32 + (sel >> 1) * 8 + lr;
    const uint32_t b_kb = (uint32_t)((sel & 1) * 16);

    __syncthreads();   // protect smem from previous phase/tile

    #define LOAD_CHUNK(ch) do {                                              \
        uint32_t _sa = T0 + ((ch) % NST) * STAGE_BYTES;                      \
        const __nv_bfloat16* _ga = A  + (size_t)m0 * LD + (ch) * 64;         \
        const __nv_bfloat16* _gb = Bm + (size_t)n0 * LD + (ch) * 64;         \
        _Pragma("unroll")                                                    \
        for (int q = 0; q < 2; q++) {                                        \
            int r = (tid + q * 256) >> 3, cc = (tid + q * 256) & 7;          \
            uint32_t off = SW128((uint32_t)(r * 128 + cc * 16));             \
            cp16(_sa        + off, _ga + (size_t)r * LD + cc * 8);           \
            cp16(_sa + 8192 + off, _gb + (size_t)r * LD + cc * 8);           \
        }                                                                    \
    } while (0)

    #define LOAD_PAIR(p) do {                                                \
        LOAD_CHUNK(2 * (p));  LOAD_CHUNK(2 * (p) + 1);                       \
        asm volatile("cp.async.commit_group;");                              \
    } while (0)

    #define LDFRAG(sa, sbb, ks, buf) do {                                    \
        _Pragma("unroll")                                                    \
        for (int mi = 0; mi < 2; mi++)                                       \
            ldsm4(af[buf][mi], (sa) + SW128((uint32_t)((a_row + mi * 16) * 128) \
                                            + (uint32_t)((ks) * 32) + a_kb)); \
        _Pragma("unroll")                                                    \
        for (int bi = 0; bi < 2; bi++)                                       \
            ldsm4(bf[buf][bi], (sbb) + SW128((uint32_t)((b_row + bi * 16) * 128) \
                                             + (uint32_t)((ks) * 32) + b_kb)); \
    } while (0)

    float acc[2][4][4];
    #pragma unroll
    for (int mi = 0; mi < 2; mi++)
        #pragma unroll
        for (int nj = 0; nj < 4; nj++)
            #pragma unroll
            for (int e = 0; e < 4; e++) acc[mi][nj][e] = 0.0f;

    LOAD_PAIR(0);
    if (NSTEP > 1) LOAD_PAIR(1);

    uint32_t af[2][2][4], bf[2][2][4];

    for (int t = 0; t < NSTEP; t++) {
        if (t < NSTEP - 1) asm volatile("cp.async.wait_group 1;");
        else               asm volatile("cp.async.wait_group 0;");
        __syncthreads();
        if (t + 2 < NSTEP) LOAD_PAIR(t + 2);

        const int ch = 2 * t + grp;
        const uint32_t sa  = T0 + (ch % NST) * STAGE_BYTES;
        const uint32_t sbb = sa + 8192;

        LDFRAG(sa, sbb, 0, 0);
        #pragma unroll
        for (int ks = 0; ks < 4; ks++) {
            const int cur = ks & 1;
            if (ks < 3) LDFRAG(sa, sbb, ks + 1, cur ^ 1);
            #pragma unroll
            for (int mi = 0; mi < 2; mi++)
                #pragma unroll
                for (int nj = 0; nj < 4; nj++)
                    mma16816(acc[mi][nj], af[cur][mi], &bf[cur][nj >> 1][(nj & 1) * 2]);
        }
    }
    #undef LDFRAG
    #undef LOAD_PAIR
    #undef LOAD_CHUNK

    // ---- cross-group reduce through smem (pitch 72 floats) ---------------
    float* Rb = (float*)sm;
    const int rrow = wm * 32 + (l >> 2);
    const int rcol = wn * 32 + 2 * (l & 3);
    __syncthreads();
    if (grp == 1) {
        #pragma unroll
        for (int mi = 0; mi < 2; mi++)
            #pragma unroll
            for (int nj = 0; nj < 4; nj++) {
                const int r = rrow + mi * 16, c = rcol + nj * 8;
                *(float2*)&Rb[r * 72 + c]       = make_float2(acc[mi][nj][0], acc[mi][nj][1]);
                *(float2*)&Rb[(r + 8) * 72 + c] = make_float2(acc[mi][nj][2], acc[mi][nj][3]);
            }
    }
    __syncthreads();

    int nzpred = 0;
    if (grp == 0) {
        #pragma unroll
        for (int mi = 0; mi < 2; mi++)
            #pragma unroll
            for (int nj = 0; nj < 4; nj++) {
                const int r = rrow + mi * 16, c = rcol + nj * 8;
                float2 p0 = *(const float2*)&Rb[r * 72 + c];
                float2 p1 = *(const float2*)&Rb[(r + 8) * 72 + c];
                acc[mi][nj][0] += p0.x;  acc[mi][nj][1] += p0.y;
                acc[mi][nj][2] += p1.x;  acc[mi][nj][3] += p1.y;
            }

        if (!ISG2) {
            // fold ck in; nz test via dist threshold (no exp needed)
            #pragma unroll
            for (int mi = 0; mi < 2; mi++)
                #pragma unroll
                for (int nj = 0; nj < 4; nj++) {
                    const int col = rcol + nj * 8;
                    const float ck0 = g_ck[n0 + col];
                    const float ck1 = g_ck[n0 + col + 1];
                    acc[mi][nj][0] += ck0;  acc[mi][nj][1] += ck1;
                    acc[mi][nj][2] += ck0;  acc[mi][nj][3] += ck1;
                    nzpred |= (acc[mi][nj][0] < DIST_ZERO_THRESH)
                            | (acc[mi][nj][1] < DIST_ZERO_THRESH)
                            | (acc[mi][nj][2] < DIST_ZERO_THRESH)
                            | (acc[mi][nj][3] < DIST_ZERO_THRESH);
                }
        }
    }

    if (!ISG2) {
        const int tile_nz = __syncthreads_or(nzpred);
        if (grp == 0) {
            const int erow = m0 + rrow;
            if (tile_nz) {
                #pragma unroll
                for (int mi = 0; mi < 2; mi++)
                    #pragma unroll
                    for (int nj = 0; nj < 4; nj++) {
                        const int col = rcol + nj * 8;
                        const int r = erow + mi * 16;
                        float v0 = __expf(-0.5f * acc[mi][nj][0]);
                        float v1 = __expf(-0.5f * acc[mi][nj][1]);
                        float v2 = __expf(-0.5f * acc[mi][nj][2]);
                        float v3 = __expf(-0.5f * acc[mi][nj][3]);
                        __nv_bfloat162 p0 = __floats2bfloat162_rn(v0, v1);
                        __nv_bfloat162 p1 = __floats2bfloat162_rn(v2, v3);
                        *(__nv_bfloat162*)&g_rbf[(size_t)r * Kn + n0 + col]       = p0;
                        *(__nv_bfloat162*)&g_rbf[(size_t)(r + 8) * Kn + n0 + col] = p1;
                    }
            } else {
                // all exps are exactly 0: store zeros (no MUFU)
                #pragma unroll
                for (int mi = 0; mi < 2; mi++)
                    #pragma unroll
                    for (int nj = 0; nj < 4; nj++) {
                        const int col = rcol + nj * 8;
                        const int r = erow + mi * 16;
                        *(uint32_t*)&g_rbf[(size_t)r * Kn + n0 + col]       = 0u;
                        *(uint32_t*)&g_rbf[(size_t)(r + 8) * Kn + n0 + col] = 0u;
                    }
            }
        }
        __syncthreads();
        return tile_nz;
    } else {
        if (grp == 0) {
            const float eps = 1e-3f;
            const int erow = m0 + rrow;
            #pragma unroll
            for (int mi = 0; mi < 2; mi++)
                #pragma unroll
                for (int nj = 0; nj < 4; nj++) {
                    const int col = n0 + rcol + nj * 8;
                    const int r = erow + mi * 16;
                    float2 o0, o1;
                    o0.x = __fdividef(1.0f, acc[mi][nj][0] + eps);
                    o0.y = __fdividef(1.0f, acc[mi][nj][1] + eps);
                    o1.x = __fdividef(1.0f, acc[mi][nj][2] + eps);
                    o1.y = __fdividef(1.0f, acc[mi][nj][3] + eps);
                    *(float2*)(out + (size_t)r * Dn + col)       = o0;
                    *(float2*)(out + (size_t)(r + 8) * Dn + col) = o1;
                }
        }
        __syncthreads();
        return 0;
    }
}

// ---------------------------------------------------------------------------
// fuse_kern: G1 tile -> PANEL-LOCAL sync (4 CTAs sharing m-panel) ->
// panel all-zero: fill 16 output rows; else: 2 full G2 tiles for the panel.
// No global barrier — panels complete independently, output overlaps G1.
// ---------------------------------------------------------------------------
__global__ void __launch_bounds__(256, 1)
fuse_kern(float* __restrict__ out) {
    extern __shared__ char sm[];
    const int c = blockIdx.x, tid = threadIdx.x;
    const int p = c & 31;      // m-panel (64 rows)
    const int q = c >> 5;      // k-block (64 of 256)

    // -------- G1: dist -> rbf tile (m0 = p*64, n0 = q*64) -------------------
    const int tile_nz = gemm_tile<false>(sm, p * 64, q * 64, nullptr);

    // -------- panel-local consensus (only 4 CTAs involved) ------------------
    if (tile_nz && tid == 0) atomicOr(&g_pnz[p], 1u);
    __threadfence();
    __syncthreads();
    if (tid == 0) {
        atomicAdd(&g_pcnt[p], 1u);
        while (atomicAdd(&g_pcnt[p], 0u) < 4u) { }
    }
    __syncthreads();
    __threadfence();

    unsigned* pflag = (unsigned*)sm;
    if (tid == 0) *pflag = g_pnz[p];
    __syncthreads();
    const unsigned panel_nz = *pflag;
    __syncthreads();

    if (!panel_nz) {
        // Entire panel's rbf rows are 0 -> h rows are 0 -> out = 1/(0+eps),
        // exactly what the full GEMM path produces on zero input.
        const float v = __fdividef(1.0f, 0.0f + 1e-3f);
        const float4 fv = make_float4(v, v, v, v);
        const int r = p * 64 + q * 16 + (tid >> 4);      // 16 rows per CTA
        float4* dst = (float4*)(out + (size_t)r * Dn + (tid & 15) * 32);
        #pragma unroll
        for (int j = 0; j < 8; j++) dst[j] = fv;
    } else {
        // Full G2 for this panel's output columns: 2 tiles of 64x64.
        gemm_tile<true>(sm, p * 64, q * 128,      out);
        gemm_tile<true>(sm, p * 64, q * 128 + 64, out);
    }

    // -------- per-panel state reset for next replay --------------------------
    __syncthreads();
    if (tid == 0) {
        __threadfence();
        unsigned d = atomicAdd(&g_pdone[p], 1u);
        if (d == 3u) {
            g_pcnt[p] = 0u;
            g_pnz[p]  = 0u;
            g_pdone[p] = 0u;
            __threadfence();
        }
    }
}

// ---------------------------------------------------------------------------
extern "C" void kernel_launch(void* const* d_in, const int* in_sizes, int n_in,
                              void* d_out, int out_size) {
    const float* x           = (const float*)d_in[0];
    const float* centers     = (const float*)d_in[1];
    const float* bandwidths  = (const float*)d_in[2];
    const float* raw_weights = (const float*)d_in[3];
    float* out = (float*)d_out;

    static bool attr_set = false;
    if (!attr_set) {
        cudaFuncSetAttribute(fuse_kern,
                             cudaFuncAttributeMaxDynamicSharedMemorySize, SMEMSZ);
        attr_set = true;
    }

    prep_all<<<416, 256>>>(x, centers, bandwidths, raw_weights);
    fuse_kern<<<NCTA, 256, SMEMSZ>>>(out);
}